// round 16
// baseline (speedup 1.0000x reference)
#include <cuda_runtime.h>
#include <cuda_fp16.h>
#include <math.h>
#include <stdint.h>

#define BATCH 32
#define SEQ 197
#define EMB 768
#define NHEAD 12
#define HDIM 64
#define QKV3 2304
#define MLPD 3072
#define NLAYER 12
#define ROWS (BATCH*SEQ)      /* 6304 */
#define ROWS_PAD 6400         /* 50*128 */
#define BHEADS (BATCH*NHEAD)  /* 384 */
#define NPATCH 196

// ---------------- scratch (static device globals) ---------------------------
__device__ float g_x[ROWS_PAD*EMB];
__device__ float g_cls[BATCH*EMB];
__device__ __half g_qkvh[(size_t)ROWS_PAD*QKV3]; // QKV, fp16
__device__ __half g_hx1[(size_t)ROWS_PAD*EMB];    // LN out, fp16
__device__ __half g_ox1[(size_t)ROWS_PAD*EMB];    // attn out, fp16
__device__ __half g_mx1[(size_t)ROWS_PAD*MLPD];   // mlp mid, fp16
__device__ __half g_wq[(size_t)NLAYER*QKV3*EMB];  // qkv_w^T fp16
__device__ __half g_wf[(size_t)NLAYER*EMB*EMB];   // fc_w^T  fp16
__device__ __half g_w1[(size_t)NLAYER*MLPD*EMB];  // w1^T    fp16
__device__ __half g_w2[(size_t)NLAYER*EMB*MLPD];  // w2^T    fp16

__device__ __forceinline__ float gelu_f(float x){
    float x3 = x*x*x;
    return 0.5f*x*(1.0f + tanhf(0.7978845608028654f*(x + 0.044715f*x3)));
}

__device__ __forceinline__ uint32_t smem_u32(const void* p){
    uint32_t a;
    asm("{ .reg .u64 t; cvta.to.shared.u64 t, %1; cvt.u32.u64 %0, t; }" : "=r"(a) : "l"(p));
    return a;
}

#define LDSM4(r0,r1,r2,r3, addr) \
    asm volatile("ldmatrix.sync.aligned.m8n8.x4.shared.b16 {%0,%1,%2,%3}, [%4];" \
        : "=r"(r0),"=r"(r1),"=r"(r2),"=r"(r3) : "r"(addr))

#define MMA16816(d, a0,a1,a2,a3, b0,b1) \
    asm volatile("mma.sync.aligned.m16n8k16.row.col.f32.f16.f16.f32 " \
        "{%0,%1,%2,%3}, {%4,%5,%6,%7}, {%8,%9}, {%0,%1,%2,%3};" \
        : "+f"((d)[0]),"+f"((d)[1]),"+f"((d)[2]),"+f"((d)[3]) \
        : "r"(a0),"r"(a1),"r"(a2),"r"(a3), "r"(b0),"r"(b1))

#define CPA16(dst, src) \
    asm volatile("cp.async.cg.shared.global [%0], [%1], 16;" :: "r"(dst), "l"(src) : "memory")
#define CPA_COMMIT() asm volatile("cp.async.commit_group;" ::: "memory")
#define CPA_WAIT0()  asm volatile("cp.async.wait_group 0;" ::: "memory")
#define CPA_WAIT1()  asm volatile("cp.async.wait_group 1;" ::: "memory")

// ---------------- tensor-core GEMM (mma.sync fp16, 3-stage cp.async) --------
#define STG_A(s) ((s)*32768)
#define STG_B(s) ((s)*32768 + 16384)
#define SM_TOTAL 98304

// epi: 0 = fp16 store to outh (stride ldo); 1 = outf += v; 2 = gelu(v+bias)->outh (stride MLPD);
//      3 = outf += v + bias
__global__ void __launch_bounds__(256,2) tgemm(
    const __half* __restrict__ A, const __half* __restrict__ Bt,
    int ldk, int NC,
    float* __restrict__ outf, int ldo, const float* __restrict__ bias,
    __half* __restrict__ outh, int epi)
{
    extern __shared__ char dsm[];
    const int tid = threadIdx.x;
    const int wid = tid >> 5;
    const int lane = tid & 31;
    const int warp_m = wid & 1;
    const int warp_n = wid >> 1;
    const int rowBase = blockIdx.y * 128;
    const int colBase = blockIdx.x * 128;
    const uint32_t sbase = smem_u32(dsm);

    const __half* Ab = A  + (size_t)rowBase * ldk;
    const __half* Bb = Bt + (size_t)colBase * ldk;

    float acc[4][4][4];
#pragma unroll
    for (int mt=0;mt<4;mt++)
#pragma unroll
      for (int nt=0;nt<4;nt++)
#pragma unroll
        for (int j=0;j<4;j++) acc[mt][nt][j]=0.f;

    const int lA_row = warp_m*64 + (lane & 15);
    const int lA_kb  = (lane >> 4) * 16;
    const int g      = lane >> 3;
    const int lB_row = warp_n*32 + (lane & 7) + (g >> 1) * 8;
    const int lB_kb  = (g & 1) * 16;

    const int ldr_r = tid >> 3;
    const int ldr_c = tid & 7;

#pragma unroll
    for (int i=0;i<4;i++){
        int r = ldr_r + i*32;
        uint32_t off = r*128 + ldr_c*16;
        off ^= (off>>3)&0x70;
        CPA16(sbase + STG_A(0) + off, Ab + (size_t)r*ldk + ldr_c*8);
        CPA16(sbase + STG_B(0) + off, Bb + (size_t)r*ldk + ldr_c*8);
    }
    CPA_COMMIT();
    if (NC > 1){
#pragma unroll
        for (int i=0;i<4;i++){
            int r = ldr_r + i*32;
            uint32_t off = r*128 + ldr_c*16;
            off ^= (off>>3)&0x70;
            CPA16(sbase + STG_A(1) + off, Ab + (size_t)r*ldk + 64 + ldr_c*8);
            CPA16(sbase + STG_B(1) + off, Bb + (size_t)r*ldk + 64 + ldr_c*8);
        }
        CPA_COMMIT();
    }

    int stage = 0;
    int wstage = 2;
    for (int c = 0; c < NC; c++){
        if (c + 2 < NC) CPA_WAIT1(); else CPA_WAIT0();
        __syncthreads();

        if (c + 2 < NC){
            int k0 = (c+2)*64;
            uint32_t wa = sbase + STG_A(wstage);
            uint32_t wb = sbase + STG_B(wstage);
#pragma unroll
            for (int i=0;i<4;i++){
                int r = ldr_r + i*32;
                uint32_t off = r*128 + ldr_c*16;
                off ^= (off>>3)&0x70;
                CPA16(wa + off, Ab + (size_t)r*ldk + k0 + ldr_c*8);
                CPA16(wb + off, Bb + (size_t)r*ldk + k0 + ldr_c*8);
            }
            CPA_COMMIT();
        }

        uint32_t sa = sbase + STG_A(stage);
        uint32_t sb = sbase + STG_B(stage);
#pragma unroll
        for (int ks=0; ks<4; ks++){
            uint32_t af[4][4], bf[2][4];
#pragma unroll
            for (int mt=0;mt<4;mt++){
                int row = lA_row + mt*16;
                uint32_t off = row*128 + ks*32 + lA_kb;
                off ^= (off>>3)&0x70;
                LDSM4(af[mt][0],af[mt][1],af[mt][2],af[mt][3], sa + off);
            }
#pragma unroll
            for (int bt=0;bt<2;bt++){
                int row = lB_row + bt*16;
                uint32_t off = row*128 + ks*32 + lB_kb;
                off ^= (off>>3)&0x70;
                LDSM4(bf[bt][0],bf[bt][1],bf[bt][2],bf[bt][3], sb + off);
            }
#pragma unroll
            for (int mt=0;mt<4;mt++)
#pragma unroll
              for (int nt=0;nt<4;nt++){
                  uint32_t b0 = bf[nt>>1][(nt&1)*2];
                  uint32_t b1 = bf[nt>>1][(nt&1)*2+1];
                  MMA16816(acc[mt][nt], af[mt][0],af[mt][1],af[mt][2],af[mt][3], b0,b1);
              }
        }

        stage = (stage + 1 == 3) ? 0 : stage + 1;
        wstage = (wstage + 1 == 3) ? 0 : wstage + 1;
    }
    __syncthreads();

    const int grp = lane >> 2;
    const int thc = (lane & 3) * 2;
#pragma unroll
    for (int mt=0;mt<4;mt++){
#pragma unroll
        for (int half=0; half<2; half++){
            int grow = rowBase + warp_m*64 + mt*16 + grp + half*8;
            if (grow >= ROWS) continue;
#pragma unroll
            for (int nt=0;nt<4;nt++){
                float v0 = acc[mt][nt][half*2+0];
                float v1 = acc[mt][nt][half*2+1];
                int gcol = colBase + warp_n*32 + nt*8 + thc;
                if (epi == 0){
                    __half2 hh; hh.x = __float2half_rn(v0); hh.y = __float2half_rn(v1);
                    *(__half2*)(outh + (size_t)grow*ldo + gcol) = hh;
                } else if (epi == 1){
                    float2* p = (float2*)(outf + (size_t)grow*EMB + gcol);
                    float2 x = *p;
                    x.x += v0; x.y += v1;
                    *p = x;
                } else if (epi == 2){
                    float t0 = gelu_f(v0 + bias[gcol]);
                    float t1 = gelu_f(v1 + bias[gcol+1]);
                    __half2 hh; hh.x = __float2half_rn(t0); hh.y = __float2half_rn(t1);
                    *(__half2*)(outh + (size_t)grow*MLPD + gcol) = hh;
                } else {
                    float2* p = (float2*)(outf + (size_t)grow*EMB + gcol);
                    float2 x = *p;
                    x.x += v0 + bias[gcol]; x.y += v1 + bias[gcol+1];
                    *p = x;
                }
            }
        }
    }
}

// ---------------- fused attention: fp16 qkv, 64-row q-tiles -----------------
// grid (4, BHEADS), block 256. Warp owns 8 q-rows.
// Phase 1: Ks(197x65) + Qs(64x65) resident -> scores in regs.
// Phase 2 (post-barrier): Ps(64x200=12800) aliased into Ks region (12805);
//          V in 32-row chunks (stride 66) through Qs region (4160 >= 2112).
#define FA_KS 0
#define FA_QS 12806
#define FA_FLOATS (FA_QS + 4160)   /* 16966 */
#define FA_SMEM (FA_FLOATS*4)      /* 67864 B */

__global__ void __launch_bounds__(256) fattn(const __half* __restrict__ qkv,
                                             __half* __restrict__ ox1)
{
    extern __shared__ float fsm[];
    float* Ks = fsm + FA_KS;
    float* Qs = fsm + FA_QS;
    float* Ps = fsm + FA_KS;   // alias after post-scores barrier (scalar access)
    float* Vs = fsm + FA_QS;   // alias: even base, stride 66 -> float2-aligned
    const int tid = threadIdx.x, wid = tid >> 5, lane = tid & 31;
    const int bh = blockIdx.y;
    const int b = bh / NHEAD, h = bh - b*NHEAD;
    const int q0 = blockIdx.x * 64;
    const __half* base = qkv + (size_t)b*SEQ*QKV3 + h*HDIM;

    // load K (197x64) stride 65
    for (int idx = tid; idx < SEQ*16; idx += 256){
        int r = idx >> 4, c4 = (idx & 15) << 2;
        uint2 u = *(const uint2*)(base + EMB + (size_t)r*QKV3 + c4);
        __half2 p0 = *(__half2*)&u.x, p1 = *(__half2*)&u.y;
        float* d = Ks + r*65 + c4;
        d[0]=__low2float(p0); d[1]=__high2float(p0);
        d[2]=__low2float(p1); d[3]=__high2float(p1);
    }
    // load Q tile (64x64) stride 65
    for (int idx = tid; idx < 64*16; idx += 256){
        int r = idx >> 4, c4 = (idx & 15) << 2;
        int qr = q0 + r;
        float* d = Qs + r*65 + c4;
        if (qr < SEQ){
            uint2 u = *(const uint2*)(base + (size_t)qr*QKV3 + c4);
            __half2 p0 = *(__half2*)&u.x, p1 = *(__half2*)&u.y;
            d[0]=__low2float(p0); d[1]=__high2float(p0);
            d[2]=__low2float(p1); d[3]=__high2float(p1);
        } else {
            d[0]=0.f; d[1]=0.f; d[2]=0.f; d[3]=0.f;
        }
    }
    __syncthreads();

    // scores: warp owns rows wid*8..+7; lane owns keys lane+32*kk, kk<7
    float s[8][7];
#pragma unroll
    for (int r=0;r<8;r++)
#pragma unroll
      for (int kk=0;kk<7;kk++) s[r][kk]=0.f;

    for (int d0=0; d0<HDIM; d0+=4){
        float k[7][4];
#pragma unroll
        for (int kk=0;kk<7;kk++){
            const float* kp = Ks + (lane+32*kk)*65 + d0;
            k[kk][0]=kp[0]; k[kk][1]=kp[1]; k[kk][2]=kp[2]; k[kk][3]=kp[3];
        }
#pragma unroll
        for (int r=0;r<8;r++){
            const float* qp = Qs + (wid*8+r)*65 + d0;
            float q0v=qp[0], q1v=qp[1], q2v=qp[2], q3v=qp[3];
#pragma unroll
            for (int kk=0;kk<7;kk++){
                s[r][kk] += q0v*k[kk][0] + q1v*k[kk][1] + q2v*k[kk][2] + q3v*k[kk][3];
            }
        }
    }

    float invs[8];
#pragma unroll
    for (int r=0;r<8;r++){
        float mx = -1e30f;
#pragma unroll
        for (int kk=0;kk<7;kk++){
            int key = lane + 32*kk;
            s[r][kk] = (key < SEQ) ? s[r][kk]*0.125f : -1e30f;
            mx = fmaxf(mx, s[r][kk]);
        }
#pragma unroll
        for (int o=16;o;o>>=1) mx = fmaxf(mx, __shfl_xor_sync(0xffffffffu, mx, o));
        float sum = 0.f;
#pragma unroll
        for (int kk=0;kk<7;kk++){
            float p = __expf(s[r][kk]-mx);
            s[r][kk] = p; sum += p;
        }
#pragma unroll
        for (int o=16;o;o>>=1) sum += __shfl_xor_sync(0xffffffffu, sum, o);
        invs[r] = 1.f/sum;
    }

    __syncthreads();   // retire all Ks/Qs reads before aliasing

#pragma unroll
    for (int r=0;r<8;r++){
#pragma unroll
        for (int kk=0;kk<7;kk++){
            int key = lane + 32*kk;
            if (key < SEQ) Ps[(wid*8+r)*200 + key] = s[r][kk];
        }
    }

    float o[8][2];
#pragma unroll
    for (int r=0;r<8;r++){ o[r][0]=0.f; o[r][1]=0.f; }

    for (int kt=0; kt<SEQ; kt+=32){
        int nrows = SEQ - kt; if (nrows > 32) nrows = 32;
        __syncthreads();
        for (int idx = tid; idx < nrows*16; idx += 256){
            int r = idx >> 4, c4 = (idx & 15) << 2;
            uint2 u = *(const uint2*)(base + 2*EMB + (size_t)(kt+r)*QKV3 + c4);
            __half2 p0 = *(__half2*)&u.x, p1 = *(__half2*)&u.y;
            float* d = Vs + r*66 + c4;
            d[0]=__low2float(p0); d[1]=__high2float(p0);
            d[2]=__low2float(p1); d[3]=__high2float(p1);
        }
        __syncthreads();
        for (int kl=0; kl<nrows; kl++){
            float2 vv = *(float2*)(Vs + kl*66 + lane*2);
#pragma unroll
            for (int r=0;r<8;r++){
                float p = Ps[(wid*8+r)*200 + kt + kl];
                o[r][0] += p*vv.x; o[r][1] += p*vv.y;
            }
        }
    }

#pragma unroll
    for (int r=0;r<8;r++){
        int qr = q0 + wid*8 + r;
        if (qr >= SEQ) continue;
        float v0 = o[r][0]*invs[r], v1 = o[r][1]*invs[r];
        __half2 hh; hh.x = __float2half_rn(v0); hh.y = __float2half_rn(v1);
        __half* orow = ox1 + ((size_t)b*SEQ + qr)*EMB;
        int col = h*HDIM + lane*2;
        *(__half2*)(orow + col) = hh;
    }
}

// ---------------- weight convert: (L,K,N) fp32 -> (L,N,K) fp16 --------------
__global__ void wconv(const float* __restrict__ src, __half* __restrict__ dst,
                      int K, int N)
{
    int l = blockIdx.z;
    src += (size_t)l*K*N;
    dst += (size_t)l*N*K;
    __shared__ float sm[32][33];
    int k0 = blockIdx.x*32, n0 = blockIdx.y*32;
#pragma unroll
    for (int i=0;i<4;i++){
        int k = k0 + threadIdx.y + i*8;
        sm[threadIdx.y + i*8][threadIdx.x] = src[(size_t)k*N + n0 + threadIdx.x];
    }
    __syncthreads();
#pragma unroll
    for (int i=0;i<4;i++){
        int n = n0 + threadIdx.y + i*8;
        int k = k0 + threadIdx.x;
        float v = sm[threadIdx.x][threadIdx.y + i*8];
        dst[(size_t)n*K + k] = __float2half_rn(v);
    }
}

// ---------------- patch-embed GEMM (fp32) -----------------------------------
__global__ __launch_bounds__(256,2) void patch_gemm(
    const float* __restrict__ img, const float* __restrict__ Bw,
    const float* __restrict__ pbias, const float* __restrict__ pos,
    float* __restrict__ X)
{
    __shared__ float As[16][132];
    __shared__ float Bs[16][132];
    const int tid = threadIdx.x;
    const int rowBase = blockIdx.y * 128;
    const int colBase = blockIdx.x * 128;
    const int ty = tid >> 4, tx = tid & 15;

    float acc[2][2][4][4];
#pragma unroll
    for (int a=0;a<2;a++)
#pragma unroll
      for (int b=0;b<2;b++)
#pragma unroll
        for (int i=0;i<4;i++)
#pragma unroll
          for (int j=0;j<4;j++) acc[a][b][i][j]=0.f;

    for (int k0 = 0; k0 < EMB; k0 += 16) {
#pragma unroll
        for (int i=0;i<2;i++){
            int idx = tid + i*256;
            int r = idx >> 2;
            int c4 = (idx & 3) << 2;
            int gr = rowBase + r;
            int gk = k0 + c4;
            int b  = gr / NPATCH;
            int n  = gr - b*NPATCH;
            int pr = n / 14, pc = n - pr*14;
            int ch = gk >> 8;
            int py = (gk >> 4) & 15;
            int px = gk & 15;
            const float* src = img + ((((size_t)(b*3+ch))*224 + pr*16+py)*224 + pc*16 + px);
            float4 v = *(const float4*)src;
            As[c4+0][r]=v.x; As[c4+1][r]=v.y; As[c4+2][r]=v.z; As[c4+3][r]=v.w;
        }
#pragma unroll
        for (int i=0;i<2;i++){
            int idx = tid + i*256;
            int r = idx >> 5;
            int c4 = (idx & 31) << 2;
            *(float4*)&Bs[r][c4] = *(const float4*)(Bw + (size_t)(k0+r)*EMB + colBase + c4);
        }
        __syncthreads();
#pragma unroll
        for (int k=0;k<16;k++){
            float av[2][4], bv[2][4];
            *(float4*)&av[0][0] = *(const float4*)&As[k][ty*4];
            *(float4*)&av[1][0] = *(const float4*)&As[k][ty*4 + 64];
            *(float4*)&bv[0][0] = *(const float4*)&Bs[k][tx*4];
            *(float4*)&bv[1][0] = *(const float4*)&Bs[k][tx*4 + 64];
#pragma unroll
            for (int a=0;a<2;a++)
#pragma unroll
              for (int i=0;i<4;i++)
#pragma unroll
                for (int b=0;b<2;b++)
#pragma unroll
                  for (int j=0;j<4;j++)
                    acc[a][b][i][j] += av[a][i]*bv[b][j];
        }
        __syncthreads();
    }

#pragma unroll
    for (int a=0;a<2;a++){
#pragma unroll
        for (int b=0;b<2;b++){
            int r0 = rowBase + ty*4 + a*64;
            int c0 = colBase + tx*4 + b*64;
#pragma unroll
            for (int i=0;i<4;i++){
                int r = r0 + i;
                int bb = r / NPATCH;
                int n  = r - bb*NPATCH;
                float* Xrow = X + ((size_t)(bb*SEQ) + 1 + n)*EMB + c0;
                const float* prow = pos + (size_t)(1+n)*EMB + c0;
#pragma unroll
                for (int j=0;j<4;j++)
                    Xrow[j] = acc[a][b][i][j] + pbias[c0+j] + prow[j];
            }
        }
    }
}

__global__ void cls_init(const float* __restrict__ cls, const float* __restrict__ pos,
                         float* __restrict__ X)
{
    int idx = blockIdx.x*256 + threadIdx.x;
    if (idx >= BATCH*EMB) return;
    int b = idx / EMB, e = idx - b*EMB;
    X[(size_t)b*SEQ*EMB + e] = cls[e] + pos[e];
}

// ---------------- layernorm -> fp16 -----------------------------------------
__global__ void ln_x1(const float* __restrict__ in, __half* __restrict__ out)
{
    int row = blockIdx.x;
    const float* p = in + (size_t)row*EMB;
    int t = threadIdx.x;
    float v[3]; float s=0.f, s2=0.f;
#pragma unroll
    for (int i=0;i<3;i++){ v[i]=p[t + i*256]; s+=v[i]; s2+=v[i]*v[i]; }
    __shared__ float sh[2][8];
#pragma unroll
    for (int o=16;o;o>>=1){ s += __shfl_xor_sync(0xffffffffu,s,o); s2 += __shfl_xor_sync(0xffffffffu,s2,o); }
    if ((t&31)==0){ sh[0][t>>5]=s; sh[1][t>>5]=s2; }
    __syncthreads();
    if (t < 32){
        s  = (t<8)? sh[0][t] : 0.f;
        s2 = (t<8)? sh[1][t] : 0.f;
#pragma unroll
        for (int o=4;o;o>>=1){ s += __shfl_xor_sync(0xffffffffu,s,o); s2 += __shfl_xor_sync(0xffffffffu,s2,o); }
        if (t==0){ sh[0][0]=s; sh[1][0]=s2; }
    }
    __syncthreads();
    float mu  = sh[0][0]*(1.f/EMB);
    float var = sh[1][0]*(1.f/EMB) - mu*mu;
    float inv = rsqrtf(var + 1e-5f);
    __half* q = out + (size_t)row*EMB;
#pragma unroll
    for (int i=0;i<3;i++){
        int e = t + i*256;
        q[e] = __float2half_rn((v[i]-mu)*inv);
    }
}

__global__ void lnfinal_k(const float* __restrict__ X, const float* __restrict__ g,
                          const float* __restrict__ bta, float* __restrict__ out)
{
    int b = blockIdx.x;
    const float* p = X + (size_t)b*SEQ*EMB;
    int t = threadIdx.x;
    float v[3]; float s=0.f, s2=0.f;
#pragma unroll
    for (int i=0;i<3;i++){ v[i]=p[t + i*256]; s+=v[i]; s2+=v[i]*v[i]; }
    __shared__ float sh[2][8];
#pragma unroll
    for (int o=16;o;o>>=1){ s += __shfl_xor_sync(0xffffffffu,s,o); s2 += __shfl_xor_sync(0xffffffffu,s2,o); }
    if ((t&31)==0){ sh[0][t>>5]=s; sh[1][t>>5]=s2; }
    __syncthreads();
    if (t < 32){
        s  = (t<8)? sh[0][t] : 0.f;
        s2 = (t<8)? sh[1][t] : 0.f;
#pragma unroll
        for (int o=4;o;o>>=1){ s += __shfl_xor_sync(0xffffffffu,s,o); s2 += __shfl_xor_sync(0xffffffffu,s2,o); }
        if (t==0){ sh[0][0]=s; sh[1][0]=s2; }
    }
    __syncthreads();
    float mu  = sh[0][0]*(1.f/EMB);
    float var = sh[1][0]*(1.f/EMB) - mu*mu;
    float inv = rsqrtf(var + 1e-5f);
#pragma unroll
    for (int i=0;i<3;i++){
        int e = t + i*256;
        out[(size_t)b*EMB + e] = (v[i]-mu)*inv*g[e] + bta[e];
    }
}

__global__ void head_k(const float* __restrict__ cls, const float* __restrict__ hw,
                       const float* __restrict__ hb, float* __restrict__ out)
{
    int t = threadIdx.x;
    if (t >= BATCH*10) return;
    int b = t/10, c = t - b*10;
    float s = __ldg(hb + c);
    const float* crow = cls + (size_t)b*EMB;
    for (int e=0;e<EMB;e++) s += crow[e]*__ldg(hw + (size_t)e*10 + c);
    out[t] = s;
}

// ---------------- launch ----------------------------------------------------
extern "C" void kernel_launch(void* const* d_in, const int* in_sizes, int n_in,
                              void* d_out, int out_size)
{
    (void)in_sizes; (void)n_in; (void)out_size;
    const float* img     = (const float*)d_in[0];
    const float* patch_w = (const float*)d_in[1];
    const float* patch_b = (const float*)d_in[2];
    const float* cls_tok = (const float*)d_in[3];
    const float* pos_emb = (const float*)d_in[4];
    const float* qkv_w   = (const float*)d_in[5];
    const float* fc_w    = (const float*)d_in[6];
    const float* mlp_w1  = (const float*)d_in[7];
    const float* mlp_b1  = (const float*)d_in[8];
    const float* mlp_w2  = (const float*)d_in[9];
    const float* mlp_b2  = (const float*)d_in[10];
    const float* ln_g    = (const float*)d_in[11];
    const float* ln_b    = (const float*)d_in[12];
    const float* head_w  = (const float*)d_in[13];
    const float* head_b  = (const float*)d_in[14];
    float* out = (float*)d_out;

    static float *x=nullptr,*clsb=nullptr;
    static __half *qkvh=nullptr,*hx1=nullptr,*ox1=nullptr,*mx1=nullptr,*wq=nullptr,*wf=nullptr,*w1=nullptr,*w2=nullptr;
    if (!x){
        cudaGetSymbolAddress((void**)&x,    g_x);
        cudaGetSymbolAddress((void**)&clsb, g_cls);
        cudaGetSymbolAddress((void**)&qkvh, g_qkvh);
        cudaGetSymbolAddress((void**)&hx1,  g_hx1);
        cudaGetSymbolAddress((void**)&ox1,  g_ox1);
        cudaGetSymbolAddress((void**)&mx1,  g_mx1);
        cudaGetSymbolAddress((void**)&wq,   g_wq);
        cudaGetSymbolAddress((void**)&wf,   g_wf);
        cudaGetSymbolAddress((void**)&w1,   g_w1);
        cudaGetSymbolAddress((void**)&w2,   g_w2);
        cudaFuncSetAttribute(tgemm, cudaFuncAttributeMaxDynamicSharedMemorySize, SM_TOTAL);
        cudaFuncSetAttribute(fattn, cudaFuncAttributeMaxDynamicSharedMemorySize, FA_SMEM);
    }

    // weight convert (fp16 transpose), all layers
    wconv<<<dim3(EMB/32,  QKV3/32, NLAYER), dim3(32,8)>>>(qkv_w,  wq, EMB,  QKV3);
    wconv<<<dim3(EMB/32,  EMB/32,  NLAYER), dim3(32,8)>>>(fc_w,   wf, EMB,  EMB);
    wconv<<<dim3(EMB/32,  MLPD/32, NLAYER), dim3(32,8)>>>(mlp_w1, w1, EMB,  MLPD);
    wconv<<<dim3(MLPD/32, EMB/32,  NLAYER), dim3(32,8)>>>(mlp_w2, w2, MLPD, EMB);

    patch_gemm<<<dim3(6,49),256>>>(img, patch_w, patch_b, pos_emb, x);
    cls_init<<<(BATCH*EMB+255)/256,256>>>(cls_tok, pos_emb, x);

    for (int l=0; l<NLAYER; l++){
        ln_x1<<<ROWS,256>>>(x, hx1);
        tgemm<<<dim3(QKV3/128, ROWS_PAD/128), 256, SM_TOTAL>>>(
            hx1, wq + (size_t)l*QKV3*EMB, EMB, 12, nullptr, QKV3, nullptr, qkvh, 0);
        fattn<<<dim3(4, BHEADS), 256, FA_SMEM>>>(qkvh, ox1);
        tgemm<<<dim3(EMB/128, ROWS_PAD/128), 256, SM_TOTAL>>>(
            ox1, wf + (size_t)l*EMB*EMB, EMB, 12, x, EMB, nullptr, nullptr, 1);
        ln_x1<<<ROWS,256>>>(x, hx1);
        tgemm<<<dim3(MLPD/128, ROWS_PAD/128), 256, SM_TOTAL>>>(
            hx1, w1 + (size_t)l*MLPD*EMB, EMB, 12, nullptr, 0,
            mlp_b1 + (size_t)l*MLPD, mx1, 2);
        tgemm<<<dim3(EMB/128, ROWS_PAD/128), 256, SM_TOTAL>>>(
            mx1, w2 + (size_t)l*EMB*MLPD, MLPD, 48, x, EMB,
            mlp_b2 + (size_t)l*EMB, nullptr, 3);
    }

    lnfinal_k<<<BATCH,256>>>(x, ln_g, ln_b, clsb);
    head_k<<<1,512>>>(clsb, head_w, head_b, out);
}

// round 17
// speedup vs baseline: 1.0401x; 1.0401x over previous
#include <cuda_runtime.h>
#include <cuda_fp16.h>
#include <math.h>
#include <stdint.h>

#define BATCH 32
#define SEQ 197
#define EMB 768
#define NHEAD 12
#define HDIM 64
#define QKV3 2304
#define MLPD 3072
#define NLAYER 12
#define ROWS (BATCH*SEQ)      /* 6304 */
#define ROWS_PAD 6400         /* 50*128 */
#define BHEADS (BATCH*NHEAD)  /* 384 */
#define NPATCH 196

// ---------------- scratch (static device globals) ---------------------------
__device__ float g_x[ROWS_PAD*EMB];
__device__ float g_cls[BATCH*EMB];
__device__ __half g_qkvh[(size_t)ROWS_PAD*QKV3]; // QKV, fp16
__device__ __half g_hx1[(size_t)ROWS_PAD*EMB];    // LN out, fp16
__device__ __half g_ox1[(size_t)ROWS_PAD*EMB];    // attn out, fp16
__device__ __half g_mx1[(size_t)ROWS_PAD*MLPD];   // mlp mid, fp16
__device__ __half g_wq[(size_t)NLAYER*QKV3*EMB];  // qkv_w^T fp16
__device__ __half g_wf[(size_t)NLAYER*EMB*EMB];   // fc_w^T  fp16
__device__ __half g_w1[(size_t)NLAYER*MLPD*EMB];  // w1^T    fp16
__device__ __half g_w2[(size_t)NLAYER*EMB*MLPD];  // w2^T    fp16

__device__ __forceinline__ float gelu_f(float x){
    float x3 = x*x*x;
    return 0.5f*x*(1.0f + tanhf(0.7978845608028654f*(x + 0.044715f*x3)));
}

__device__ __forceinline__ uint32_t smem_u32(const void* p){
    uint32_t a;
    asm("{ .reg .u64 t; cvta.to.shared.u64 t, %1; cvt.u32.u64 %0, t; }" : "=r"(a) : "l"(p));
    return a;
}

#define LDSM4(r0,r1,r2,r3, addr) \
    asm volatile("ldmatrix.sync.aligned.m8n8.x4.shared.b16 {%0,%1,%2,%3}, [%4];" \
        : "=r"(r0),"=r"(r1),"=r"(r2),"=r"(r3) : "r"(addr))

#define MMA16816(d, a0,a1,a2,a3, b0,b1) \
    asm volatile("mma.sync.aligned.m16n8k16.row.col.f32.f16.f16.f32 " \
        "{%0,%1,%2,%3}, {%4,%5,%6,%7}, {%8,%9}, {%0,%1,%2,%3};" \
        : "+f"((d)[0]),"+f"((d)[1]),"+f"((d)[2]),"+f"((d)[3]) \
        : "r"(a0),"r"(a1),"r"(a2),"r"(a3), "r"(b0),"r"(b1))

#define CPA16(dst, src) \
    asm volatile("cp.async.cg.shared.global [%0], [%1], 16;" :: "r"(dst), "l"(src) : "memory")
#define CPA_COMMIT() asm volatile("cp.async.commit_group;" ::: "memory")
#define CPA_WAIT0()  asm volatile("cp.async.wait_group 0;" ::: "memory")
#define CPA_WAIT1()  asm volatile("cp.async.wait_group 1;" ::: "memory")

// ---------------- tensor-core GEMM (mma.sync fp16, 3-stage cp.async) --------
#define STG_A(s) ((s)*32768)
#define STG_B(s) ((s)*32768 + 16384)
#define SM_TOTAL 98304

// epi: 0 = fp16 store to outh (stride ldo); 1 = outf += v; 2 = gelu(v+bias)->outh (stride MLPD);
//      3 = outf += v + bias
__global__ void __launch_bounds__(256,2) tgemm(
    const __half* __restrict__ A, const __half* __restrict__ Bt,
    int ldk, int NC,
    float* __restrict__ outf, int ldo, const float* __restrict__ bias,
    __half* __restrict__ outh, int epi)
{
    extern __shared__ char dsm[];
    const int tid = threadIdx.x;
    const int wid = tid >> 5;
    const int lane = tid & 31;
    const int warp_m = wid & 1;
    const int warp_n = wid >> 1;
    const int rowBase = blockIdx.y * 128;
    const int colBase = blockIdx.x * 128;
    const uint32_t sbase = smem_u32(dsm);

    const __half* Ab = A  + (size_t)rowBase * ldk;
    const __half* Bb = Bt + (size_t)colBase * ldk;

    float acc[4][4][4];
#pragma unroll
    for (int mt=0;mt<4;mt++)
#pragma unroll
      for (int nt=0;nt<4;nt++)
#pragma unroll
        for (int j=0;j<4;j++) acc[mt][nt][j]=0.f;

    const int lA_row = warp_m*64 + (lane & 15);
    const int lA_kb  = (lane >> 4) * 16;
    const int g      = lane >> 3;
    const int lB_row = warp_n*32 + (lane & 7) + (g >> 1) * 8;
    const int lB_kb  = (g & 1) * 16;

    const int ldr_r = tid >> 3;
    const int ldr_c = tid & 7;

#pragma unroll
    for (int i=0;i<4;i++){
        int r = ldr_r + i*32;
        uint32_t off = r*128 + ldr_c*16;
        off ^= (off>>3)&0x70;
        CPA16(sbase + STG_A(0) + off, Ab + (size_t)r*ldk + ldr_c*8);
        CPA16(sbase + STG_B(0) + off, Bb + (size_t)r*ldk + ldr_c*8);
    }
    CPA_COMMIT();
    if (NC > 1){
#pragma unroll
        for (int i=0;i<4;i++){
            int r = ldr_r + i*32;
            uint32_t off = r*128 + ldr_c*16;
            off ^= (off>>3)&0x70;
            CPA16(sbase + STG_A(1) + off, Ab + (size_t)r*ldk + 64 + ldr_c*8);
            CPA16(sbase + STG_B(1) + off, Bb + (size_t)r*ldk + 64 + ldr_c*8);
        }
        CPA_COMMIT();
    }

    int stage = 0;
    int wstage = 2;
    for (int c = 0; c < NC; c++){
        if (c + 2 < NC) CPA_WAIT1(); else CPA_WAIT0();
        __syncthreads();

        if (c + 2 < NC){
            int k0 = (c+2)*64;
            uint32_t wa = sbase + STG_A(wstage);
            uint32_t wb = sbase + STG_B(wstage);
#pragma unroll
            for (int i=0;i<4;i++){
                int r = ldr_r + i*32;
                uint32_t off = r*128 + ldr_c*16;
                off ^= (off>>3)&0x70;
                CPA16(wa + off, Ab + (size_t)r*ldk + k0 + ldr_c*8);
                CPA16(wb + off, Bb + (size_t)r*ldk + k0 + ldr_c*8);
            }
            CPA_COMMIT();
        }

        uint32_t sa = sbase + STG_A(stage);
        uint32_t sb = sbase + STG_B(stage);
#pragma unroll
        for (int ks=0; ks<4; ks++){
            uint32_t af[4][4], bf[2][4];
#pragma unroll
            for (int mt=0;mt<4;mt++){
                int row = lA_row + mt*16;
                uint32_t off = row*128 + ks*32 + lA_kb;
                off ^= (off>>3)&0x70;
                LDSM4(af[mt][0],af[mt][1],af[mt][2],af[mt][3], sa + off);
            }
#pragma unroll
            for (int bt=0;bt<2;bt++){
                int row = lB_row + bt*16;
                uint32_t off = row*128 + ks*32 + lB_kb;
                off ^= (off>>3)&0x70;
                LDSM4(bf[bt][0],bf[bt][1],bf[bt][2],bf[bt][3], sb + off);
            }
#pragma unroll
            for (int mt=0;mt<4;mt++)
#pragma unroll
              for (int nt=0;nt<4;nt++){
                  uint32_t b0 = bf[nt>>1][(nt&1)*2];
                  uint32_t b1 = bf[nt>>1][(nt&1)*2+1];
                  MMA16816(acc[mt][nt], af[mt][0],af[mt][1],af[mt][2],af[mt][3], b0,b1);
              }
        }

        stage = (stage + 1 == 3) ? 0 : stage + 1;
        wstage = (wstage + 1 == 3) ? 0 : wstage + 1;
    }
    __syncthreads();

    const int grp = lane >> 2;
    const int thc = (lane & 3) * 2;
#pragma unroll
    for (int mt=0;mt<4;mt++){
#pragma unroll
        for (int half=0; half<2; half++){
            int grow = rowBase + warp_m*64 + mt*16 + grp + half*8;
            if (grow >= ROWS) continue;
#pragma unroll
            for (int nt=0;nt<4;nt++){
                float v0 = acc[mt][nt][half*2+0];
                float v1 = acc[mt][nt][half*2+1];
                int gcol = colBase + warp_n*32 + nt*8 + thc;
                if (epi == 0){
                    __half2 hh; hh.x = __float2half_rn(v0); hh.y = __float2half_rn(v1);
                    *(__half2*)(outh + (size_t)grow*ldo + gcol) = hh;
                } else if (epi == 1){
                    float2* p = (float2*)(outf + (size_t)grow*EMB + gcol);
                    float2 x = *p;
                    x.x += v0; x.y += v1;
                    *p = x;
                } else if (epi == 2){
                    float t0 = gelu_f(v0 + bias[gcol]);
                    float t1 = gelu_f(v1 + bias[gcol+1]);
                    __half2 hh; hh.x = __float2half_rn(t0); hh.y = __float2half_rn(t1);
                    *(__half2*)(outh + (size_t)grow*MLPD + gcol) = hh;
                } else {
                    float2* p = (float2*)(outf + (size_t)grow*EMB + gcol);
                    float2 x = *p;
                    x.x += v0 + bias[gcol]; x.y += v1 + bias[gcol+1];
                    *p = x;
                }
            }
        }
    }
}

// ---------------- fused attention: fp16 qkv, 32-row q-tiles (proven shape) --
// grid (7, BHEADS), block 256. Warp owns 4 q-rows.
// Phase 1: Ks(197x65) + Qs(32x65) resident -> scores in regs.
// Phase 2 (post-barrier): Ps(32x200) aliased into Ks region;
//          V in 32-row chunks (stride 66, 8B-aligned) through Qs region.
#define FA_KS 0
#define FA_QS 12806
#define FA_FLOATS (FA_QS + 2112)   /* 14918 */
#define FA_SMEM (FA_FLOATS*4)      /* 59672 B */

__global__ void __launch_bounds__(256) fattn(const __half* __restrict__ qkv,
                                             __half* __restrict__ ox1)
{
    extern __shared__ float fsm[];
    float* Ks = fsm + FA_KS;
    float* Qs = fsm + FA_QS;
    float* Ps = fsm + FA_KS;   // alias after post-scores barrier (scalar access)
    float* Vs = fsm + FA_QS;   // alias: even base, stride 66 -> float2-aligned
    const int tid = threadIdx.x, wid = tid >> 5, lane = tid & 31;
    const int bh = blockIdx.y;
    const int b = bh / NHEAD, h = bh - b*NHEAD;
    const int q0 = blockIdx.x * 32;
    const __half* base = qkv + (size_t)b*SEQ*QKV3 + h*HDIM;

    // load K (197x64) stride 65
    for (int idx = tid; idx < SEQ*16; idx += 256){
        int r = idx >> 4, c4 = (idx & 15) << 2;
        uint2 u = *(const uint2*)(base + EMB + (size_t)r*QKV3 + c4);
        __half2 p0 = *(__half2*)&u.x, p1 = *(__half2*)&u.y;
        float* d = Ks + r*65 + c4;
        d[0]=__low2float(p0); d[1]=__high2float(p0);
        d[2]=__low2float(p1); d[3]=__high2float(p1);
    }
    // load Q tile (32x64) stride 65
    for (int idx = tid; idx < 32*16; idx += 256){
        int r = idx >> 4, c4 = (idx & 15) << 2;
        int qr = q0 + r;
        float* d = Qs + r*65 + c4;
        if (qr < SEQ){
            uint2 u = *(const uint2*)(base + (size_t)qr*QKV3 + c4);
            __half2 p0 = *(__half2*)&u.x, p1 = *(__half2*)&u.y;
            d[0]=__low2float(p0); d[1]=__high2float(p0);
            d[2]=__low2float(p1); d[3]=__high2float(p1);
        } else {
            d[0]=0.f; d[1]=0.f; d[2]=0.f; d[3]=0.f;
        }
    }
    __syncthreads();

    // scores: warp owns rows wid*4..+3; lane owns keys lane+32*kk, kk<7
    float s[4][7];
#pragma unroll
    for (int r=0;r<4;r++)
#pragma unroll
      for (int kk=0;kk<7;kk++) s[r][kk]=0.f;

    for (int d0=0; d0<HDIM; d0+=4){
        float q[4][4], k[7][4];
#pragma unroll
        for (int r=0;r<4;r++){
            const float* qp = Qs + (wid*4+r)*65 + d0;
            q[r][0]=qp[0]; q[r][1]=qp[1]; q[r][2]=qp[2]; q[r][3]=qp[3];
        }
#pragma unroll
        for (int kk=0;kk<7;kk++){
            const float* kp = Ks + (lane+32*kk)*65 + d0;
            k[kk][0]=kp[0]; k[kk][1]=kp[1]; k[kk][2]=kp[2]; k[kk][3]=kp[3];
        }
#pragma unroll
        for (int r=0;r<4;r++)
#pragma unroll
          for (int kk=0;kk<7;kk++)
#pragma unroll
            for (int j=0;j<4;j++)
                s[r][kk] += q[r][j]*k[kk][j];
    }

    float invs[4];
#pragma unroll
    for (int r=0;r<4;r++){
        float mx = -1e30f;
#pragma unroll
        for (int kk=0;kk<7;kk++){
            int key = lane + 32*kk;
            s[r][kk] = (key < SEQ) ? s[r][kk]*0.125f : -1e30f;
            mx = fmaxf(mx, s[r][kk]);
        }
#pragma unroll
        for (int o=16;o;o>>=1) mx = fmaxf(mx, __shfl_xor_sync(0xffffffffu, mx, o));
        float sum = 0.f;
#pragma unroll
        for (int kk=0;kk<7;kk++){
            float p = __expf(s[r][kk]-mx);
            s[r][kk] = p; sum += p;
        }
#pragma unroll
        for (int o=16;o;o>>=1) sum += __shfl_xor_sync(0xffffffffu, sum, o);
        invs[r] = 1.f/sum;
    }

    __syncthreads();   // retire all Ks/Qs reads before aliasing

#pragma unroll
    for (int r=0;r<4;r++){
#pragma unroll
        for (int kk=0;kk<7;kk++){
            int key = lane + 32*kk;
            if (key < SEQ) Ps[(wid*4+r)*200 + key] = s[r][kk];
        }
    }

    float o[4][2];
#pragma unroll
    for (int r=0;r<4;r++){ o[r][0]=0.f; o[r][1]=0.f; }

    for (int kt=0; kt<SEQ; kt+=32){
        int nrows = SEQ - kt; if (nrows > 32) nrows = 32;
        __syncthreads();
        for (int idx = tid; idx < nrows*16; idx += 256){
            int r = idx >> 4, c4 = (idx & 15) << 2;
            uint2 u = *(const uint2*)(base + 2*EMB + (size_t)(kt+r)*QKV3 + c4);
            __half2 p0 = *(__half2*)&u.x, p1 = *(__half2*)&u.y;
            float* d = Vs + r*66 + c4;
            d[0]=__low2float(p0); d[1]=__high2float(p0);
            d[2]=__low2float(p1); d[3]=__high2float(p1);
        }
        __syncthreads();
        for (int kl=0; kl<nrows; kl++){
            float2 vv = *(float2*)(Vs + kl*66 + lane*2);
#pragma unroll
            for (int r=0;r<4;r++){
                float p = Ps[(wid*4+r)*200 + kt + kl];
                o[r][0] += p*vv.x; o[r][1] += p*vv.y;
            }
        }
    }

#pragma unroll
    for (int r=0;r<4;r++){
        int qr = q0 + wid*4 + r;
        if (qr >= SEQ) continue;
        float v0 = o[r][0]*invs[r], v1 = o[r][1]*invs[r];
        __half2 hh; hh.x = __float2half_rn(v0); hh.y = __float2half_rn(v1);
        __half* orow = ox1 + ((size_t)b*SEQ + qr)*EMB;
        int col = h*HDIM + lane*2;
        *(__half2*)(orow + col) = hh;
    }
}

// ---------------- weight convert: (L,K,N) fp32 -> (L,N,K) fp16 --------------
__global__ void wconv(const float* __restrict__ src, __half* __restrict__ dst,
                      int K, int N)
{
    int l = blockIdx.z;
    src += (size_t)l*K*N;
    dst += (size_t)l*N*K;
    __shared__ float sm[32][33];
    int k0 = blockIdx.x*32, n0 = blockIdx.y*32;
#pragma unroll
    for (int i=0;i<4;i++){
        int k = k0 + threadIdx.y + i*8;
        sm[threadIdx.y + i*8][threadIdx.x] = src[(size_t)k*N + n0 + threadIdx.x];
    }
    __syncthreads();
#pragma unroll
    for (int i=0;i<4;i++){
        int n = n0 + threadIdx.y + i*8;
        int k = k0 + threadIdx.x;
        float v = sm[threadIdx.x][threadIdx.y + i*8];
        dst[(size_t)n*K + k] = __float2half_rn(v);
    }
}

// ---------------- patch-embed GEMM (fp32) -----------------------------------
__global__ __launch_bounds__(256,2) void patch_gemm(
    const float* __restrict__ img, const float* __restrict__ Bw,
    const float* __restrict__ pbias, const float* __restrict__ pos,
    float* __restrict__ X)
{
    __shared__ float As[16][132];
    __shared__ float Bs[16][132];
    const int tid = threadIdx.x;
    const int rowBase = blockIdx.y * 128;
    const int colBase = blockIdx.x * 128;
    const int ty = tid >> 4, tx = tid & 15;

    float acc[2][2][4][4];
#pragma unroll
    for (int a=0;a<2;a++)
#pragma unroll
      for (int b=0;b<2;b++)
#pragma unroll
        for (int i=0;i<4;i++)
#pragma unroll
          for (int j=0;j<4;j++) acc[a][b][i][j]=0.f;

    for (int k0 = 0; k0 < EMB; k0 += 16) {
#pragma unroll
        for (int i=0;i<2;i++){
            int idx = tid + i*256;
            int r = idx >> 2;
            int c4 = (idx & 3) << 2;
            int gr = rowBase + r;
            int gk = k0 + c4;
            int b  = gr / NPATCH;
            int n  = gr - b*NPATCH;
            int pr = n / 14, pc = n - pr*14;
            int ch = gk >> 8;
            int py = (gk >> 4) & 15;
            int px = gk & 15;
            const float* src = img + ((((size_t)(b*3+ch))*224 + pr*16+py)*224 + pc*16 + px);
            float4 v = *(const float4*)src;
            As[c4+0][r]=v.x; As[c4+1][r]=v.y; As[c4+2][r]=v.z; As[c4+3][r]=v.w;
        }
#pragma unroll
        for (int i=0;i<2;i++){
            int idx = tid + i*256;
            int r = idx >> 5;
            int c4 = (idx & 31) << 2;
            *(float4*)&Bs[r][c4] = *(const float4*)(Bw + (size_t)(k0+r)*EMB + colBase + c4);
        }
        __syncthreads();
#pragma unroll
        for (int k=0;k<16;k++){
            float av[2][4], bv[2][4];
            *(float4*)&av[0][0] = *(const float4*)&As[k][ty*4];
            *(float4*)&av[1][0] = *(const float4*)&As[k][ty*4 + 64];
            *(float4*)&bv[0][0] = *(const float4*)&Bs[k][tx*4];
            *(float4*)&bv[1][0] = *(const float4*)&Bs[k][tx*4 + 64];
#pragma unroll
            for (int a=0;a<2;a++)
#pragma unroll
              for (int i=0;i<4;i++)
#pragma unroll
                for (int b=0;b<2;b++)
#pragma unroll
                  for (int j=0;j<4;j++)
                    acc[a][b][i][j] += av[a][i]*bv[b][j];
        }
        __syncthreads();
    }

#pragma unroll
    for (int a=0;a<2;a++){
#pragma unroll
        for (int b=0;b<2;b++){
            int r0 = rowBase + ty*4 + a*64;
            int c0 = colBase + tx*4 + b*64;
#pragma unroll
            for (int i=0;i<4;i++){
                int r = r0 + i;
                int bb = r / NPATCH;
                int n  = r - bb*NPATCH;
                float* Xrow = X + ((size_t)(bb*SEQ) + 1 + n)*EMB + c0;
                const float* prow = pos + (size_t)(1+n)*EMB + c0;
#pragma unroll
                for (int j=0;j<4;j++)
                    Xrow[j] = acc[a][b][i][j] + pbias[c0+j] + prow[j];
            }
        }
    }
}

__global__ void cls_init(const float* __restrict__ cls, const float* __restrict__ pos,
                         float* __restrict__ X)
{
    int idx = blockIdx.x*256 + threadIdx.x;
    if (idx >= BATCH*EMB) return;
    int b = idx / EMB, e = idx - b*EMB;
    X[(size_t)b*SEQ*EMB + e] = cls[e] + pos[e];
}

// ---------------- layernorm -> fp16 -----------------------------------------
__global__ void ln_x1(const float* __restrict__ in, __half* __restrict__ out)
{
    int row = blockIdx.x;
    const float* p = in + (size_t)row*EMB;
    int t = threadIdx.x;
    float v[3]; float s=0.f, s2=0.f;
#pragma unroll
    for (int i=0;i<3;i++){ v[i]=p[t + i*256]; s+=v[i]; s2+=v[i]*v[i]; }
    __shared__ float sh[2][8];
#pragma unroll
    for (int o=16;o;o>>=1){ s += __shfl_xor_sync(0xffffffffu,s,o); s2 += __shfl_xor_sync(0xffffffffu,s2,o); }
    if ((t&31)==0){ sh[0][t>>5]=s; sh[1][t>>5]=s2; }
    __syncthreads();
    if (t < 32){
        s  = (t<8)? sh[0][t] : 0.f;
        s2 = (t<8)? sh[1][t] : 0.f;
#pragma unroll
        for (int o=4;o;o>>=1){ s += __shfl_xor_sync(0xffffffffu,s,o); s2 += __shfl_xor_sync(0xffffffffu,s2,o); }
        if (t==0){ sh[0][0]=s; sh[1][0]=s2; }
    }
    __syncthreads();
    float mu  = sh[0][0]*(1.f/EMB);
    float var = sh[1][0]*(1.f/EMB) - mu*mu;
    float inv = rsqrtf(var + 1e-5f);
    __half* q = out + (size_t)row*EMB;
#pragma unroll
    for (int i=0;i<3;i++){
        int e = t + i*256;
        q[e] = __float2half_rn((v[i]-mu)*inv);
    }
}

__global__ void lnfinal_k(const float* __restrict__ X, const float* __restrict__ g,
                          const float* __restrict__ bta, float* __restrict__ out)
{
    int b = blockIdx.x;
    const float* p = X + (size_t)b*SEQ*EMB;
    int t = threadIdx.x;
    float v[3]; float s=0.f, s2=0.f;
#pragma unroll
    for (int i=0;i<3;i++){ v[i]=p[t + i*256]; s+=v[i]; s2+=v[i]*v[i]; }
    __shared__ float sh[2][8];
#pragma unroll
    for (int o=16;o;o>>=1){ s += __shfl_xor_sync(0xffffffffu,s,o); s2 += __shfl_xor_sync(0xffffffffu,s2,o); }
    if ((t&31)==0){ sh[0][t>>5]=s; sh[1][t>>5]=s2; }
    __syncthreads();
    if (t < 32){
        s  = (t<8)? sh[0][t] : 0.f;
        s2 = (t<8)? sh[1][t] : 0.f;
#pragma unroll
        for (int o=4;o;o>>=1){ s += __shfl_xor_sync(0xffffffffu,s,o); s2 += __shfl_xor_sync(0xffffffffu,s2,o); }
        if (t==0){ sh[0][0]=s; sh[1][0]=s2; }
    }
    __syncthreads();
    float mu  = sh[0][0]*(1.f/EMB);
    float var = sh[1][0]*(1.f/EMB) - mu*mu;
    float inv = rsqrtf(var + 1e-5f);
#pragma unroll
    for (int i=0;i<3;i++){
        int e = t + i*256;
        out[(size_t)b*EMB + e] = (v[i]-mu)*inv*g[e] + bta[e];
    }
}

__global__ void head_k(const float* __restrict__ cls, const float* __restrict__ hw,
                       const float* __restrict__ hb, float* __restrict__ out)
{
    int t = threadIdx.x;
    if (t >= BATCH*10) return;
    int b = t/10, c = t - b*10;
    float s = __ldg(hb + c);
    const float* crow = cls + (size_t)b*EMB;
    for (int e=0;e<EMB;e++) s += crow[e]*__ldg(hw + (size_t)e*10 + c);
    out[t] = s;
}

// ---------------- launch ----------------------------------------------------
extern "C" void kernel_launch(void* const* d_in, const int* in_sizes, int n_in,
                              void* d_out, int out_size)
{
    (void)in_sizes; (void)n_in; (void)out_size;
    const float* img     = (const float*)d_in[0];
    const float* patch_w = (const float*)d_in[1];
    const float* patch_b = (const float*)d_in[2];
    const float* cls_tok = (const float*)d_in[3];
    const float* pos_emb = (const float*)d_in[4];
    const float* qkv_w   = (const float*)d_in[5];
    const float* fc_w    = (const float*)d_in[6];
    const float* mlp_w1  = (const float*)d_in[7];
    const float* mlp_b1  = (const float*)d_in[8];
    const float* mlp_w2  = (const float*)d_in[9];
    const float* mlp_b2  = (const float*)d_in[10];
    const float* ln_g    = (const float*)d_in[11];
    const float* ln_b    = (const float*)d_in[12];
    const float* head_w  = (const float*)d_in[13];
    const float* head_b  = (const float*)d_in[14];
    float* out = (float*)d_out;

    static float *x=nullptr,*clsb=nullptr;
    static __half *qkvh=nullptr,*hx1=nullptr,*ox1=nullptr,*mx1=nullptr,*wq=nullptr,*wf=nullptr,*w1=nullptr,*w2=nullptr;
    if (!x){
        cudaGetSymbolAddress((void**)&x,    g_x);
        cudaGetSymbolAddress((void**)&clsb, g_cls);
        cudaGetSymbolAddress((void**)&qkvh, g_qkvh);
        cudaGetSymbolAddress((void**)&hx1,  g_hx1);
        cudaGetSymbolAddress((void**)&ox1,  g_ox1);
        cudaGetSymbolAddress((void**)&mx1,  g_mx1);
        cudaGetSymbolAddress((void**)&wq,   g_wq);
        cudaGetSymbolAddress((void**)&wf,   g_wf);
        cudaGetSymbolAddress((void**)&w1,   g_w1);
        cudaGetSymbolAddress((void**)&w2,   g_w2);
        cudaFuncSetAttribute(tgemm, cudaFuncAttributeMaxDynamicSharedMemorySize, SM_TOTAL);
        cudaFuncSetAttribute(fattn, cudaFuncAttributeMaxDynamicSharedMemorySize, FA_SMEM);
    }

    // weight convert (fp16 transpose), all layers
    wconv<<<dim3(EMB/32,  QKV3/32, NLAYER), dim3(32,8)>>>(qkv_w,  wq, EMB,  QKV3);
    wconv<<<dim3(EMB/32,  EMB/32,  NLAYER), dim3(32,8)>>>(fc_w,   wf, EMB,  EMB);
    wconv<<<dim3(EMB/32,  MLPD/32, NLAYER), dim3(32,8)>>>(mlp_w1, w1, EMB,  MLPD);
    wconv<<<dim3(MLPD/32, EMB/32,  NLAYER), dim3(32,8)>>>(mlp_w2, w2, MLPD, EMB);

    patch_gemm<<<dim3(6,49),256>>>(img, patch_w, patch_b, pos_emb, x);
    cls_init<<<(BATCH*EMB+255)/256,256>>>(cls_tok, pos_emb, x);

    for (int l=0; l<NLAYER; l++){
        ln_x1<<<ROWS,256>>>(x, hx1);
        tgemm<<<dim3(QKV3/128, ROWS_PAD/128), 256, SM_TOTAL>>>(
            hx1, wq + (size_t)l*QKV3*EMB, EMB, 12, nullptr, QKV3, nullptr, qkvh, 0);
        fattn<<<dim3(7, BHEADS), 256, FA_SMEM>>>(qkvh, ox1);
        tgemm<<<dim3(EMB/128, ROWS_PAD/128), 256, SM_TOTAL>>>(
            ox1, wf + (size_t)l*EMB*EMB, EMB, 12, x, EMB, nullptr, nullptr, 1);
        ln_x1<<<ROWS,256>>>(x, hx1);
        tgemm<<<dim3(MLPD/128, ROWS_PAD/128), 256, SM_TOTAL>>>(
            hx1, w1 + (size_t)l*MLPD*EMB, EMB, 12, nullptr, 0,
            mlp_b1 + (size_t)l*MLPD, mx1, 2);
        tgemm<<<dim3(EMB/128, ROWS_PAD/128), 256, SM_TOTAL>>>(
            mx1, w2 + (size_t)l*EMB*MLPD, MLPD, 48, x, EMB,
            mlp_b2 + (size_t)l*EMB, nullptr, 3);
    }

    lnfinal_k<<<BATCH,256>>>(x, ln_g, ln_b, clsb);
    head_k<<<1,512>>>(clsb, head_w, head_b, out);
}